// round 2
// baseline (speedup 1.0000x reference)
#include <cuda_runtime.h>
#include <float.h>

// ---------------------------------------------------------------------------
// OneHotEncoding via spatial binning (counting sort + expanding-ring NN search)
// Outputs (concatenated float32 in d_out, validated in round 1):
//   [0, 3L)         input_tensor rows (X, Y, one_hot)
//   [3L, 3L+2B)     closest_points
//   [3L+2B, 3L+3B)  min_index as float
// ---------------------------------------------------------------------------

#define G      128
#define NBINS  (G * G)
#define MAXL   1100000
#define CELL   (10.0f / (float)G)
#define INVC   ((float)G / 10.0f)

__device__ int    g_count[NBINS];
__device__ int    g_start[NBINS + 1];
__device__ int    g_cursor[NBINS];
__device__ float2 g_sxy[MAXL];
__device__ int    g_sidx[MAXL];

__device__ __forceinline__ int bin_of(float x, float y) {
    int bx = (int)(x * INVC); bx = min(max(bx, 0), G - 1);
    int by = (int)(y * INVC); by = min(max(by, 0), G - 1);
    return by * G + bx;
}

__global__ void zero_counts() {
    int i = blockIdx.x * blockDim.x + threadIdx.x;
    if (i < NBINS) g_count[i] = 0;
}

// Pass 1: histogram bins + write input_tensor rows (X, Y, 0)
__global__ void __launch_bounds__(256)
bin_count(const float* __restrict__ mesh, float* __restrict__ out, int L)
{
    for (int i = blockIdx.x * blockDim.x + threadIdx.x; i < L;
         i += gridDim.x * blockDim.x) {
        float2 p = reinterpret_cast<const float2*>(mesh)[i];
        out[3 * i + 0] = p.x;
        out[3 * i + 1] = p.y;
        out[3 * i + 2] = 0.0f;
        atomicAdd(&g_count[bin_of(p.x, p.y)], 1);
    }
}

// Pass 2: exclusive prefix scan of 16384 bin counts (single block)
__global__ void __launch_bounds__(256)
scan_bins(int L)
{
    __shared__ int s[256];
    const int t = threadIdx.x;
    const int base = t * (NBINS / 256);          // 64 bins per thread

    int sum = 0;
    for (int k = 0; k < NBINS / 256; k++) sum += g_count[base + k];
    s[t] = sum;
    __syncthreads();

    for (int off = 1; off < 256; off <<= 1) {    // Hillis-Steele inclusive
        int v = (t >= off) ? s[t - off] : 0;
        __syncthreads();
        s[t] += v;
        __syncthreads();
    }

    int running = (t == 0) ? 0 : s[t - 1];       // exclusive
    for (int k = 0; k < NBINS / 256; k++) {
        g_start[base + k]  = running;
        g_cursor[base + k] = running;
        running += g_count[base + k];
    }
    if (t == 255) g_start[NBINS] = running;
}

// Pass 3: scatter points into bin-sorted order (coords + original index)
__global__ void __launch_bounds__(256)
bin_scatter(const float* __restrict__ mesh, int L)
{
    for (int i = blockIdx.x * blockDim.x + threadIdx.x; i < L;
         i += gridDim.x * blockDim.x) {
        float2 p = reinterpret_cast<const float2*>(mesh)[i];
        int pos = atomicAdd(&g_cursor[bin_of(p.x, p.y)], 1);
        g_sxy[pos]  = p;
        g_sidx[pos] = i;
    }
}

// Pass 4: one warp per receiver, expanding Chebyshev-ring search.
__global__ void __launch_bounds__(256)
nn_search(const float* __restrict__ mesh,
          const float* __restrict__ recv,
          float* __restrict__ out,
          int L, int B, long long out_size)
{
    const int warp = threadIdx.x >> 5;
    const int lane = threadIdx.x & 31;
    const int b = blockIdx.x * 8 + warp;
    if (b >= B) return;

    const float rx = recv[3 * b + 0];
    const float ry = recv[3 * b + 1];

    int bx = (int)(rx * INVC); bx = min(max(bx, 0), G - 1);
    int by = (int)(ry * INVC); by = min(max(by, 0), G - 1);

    float vmin = FLT_MAX;
    int   imin = 0x7fffffff;

    auto scan_seg = [&](int b0, int b1) {
        const int j0 = g_start[b0];
        const int j1 = g_start[b1 + 1];
        for (int j = j0 + lane; j < j1; j += 32) {
            float2 p = g_sxy[j];
            const float dx = p.x - rx;
            const float dy = p.y - ry;
            const float v  = fmaf(dx, dx, dy * dy);
            const int idx  = g_sidx[j];
            if (v < vmin || (v == vmin && idx < imin)) { vmin = v; imin = idx; }
        }
    };

    for (int r = 0; r < G; r++) {
        if (r >= 1) {
            // warp-wide best so far; conservative lower bound for ring r
            float wmin = vmin;
            #pragma unroll
            for (int o = 16; o; o >>= 1)
                wmin = fminf(wmin, __shfl_xor_sync(0xffffffffu, wmin, o));
            const float bound = (float)(r - 1) * CELL;
            if (bound * bound > wmin) break;   // strict: keeps equal-dist ties
        }
        for (int dy = -r; dy <= r; dy++) {
            const int y = by + dy;
            if (y < 0 || y >= G) continue;
            if (dy == -r || dy == r) {
                const int x0 = max(bx - r, 0);
                const int x1 = min(bx + r, G - 1);
                scan_seg(y * G + x0, y * G + x1);
            } else {
                int x = bx - r;
                if (x >= 0) scan_seg(y * G + x, y * G + x);
                x = bx + r;
                if (x < G && r > 0) scan_seg(y * G + x, y * G + x);
            }
        }
    }

    // final warp reduce with first-index tie-break
    #pragma unroll
    for (int o = 16; o; o >>= 1) {
        const float ov = __shfl_xor_sync(0xffffffffu, vmin, o);
        const int   oi = __shfl_xor_sync(0xffffffffu, imin, o);
        if (ov < vmin || (ov == vmin && oi < imin)) { vmin = ov; imin = oi; }
    }

    if (lane == 0) {
        const int mi = imin;
        const long long base1 = 3LL * L;
        out[3LL * mi + 2] = 1.0f;
        if (b == 0 && B > 1) out[2] = 1.0f;
        if (out_size >= base1 + 2LL * B) {
            out[base1 + 2LL * b + 0] = mesh[2 * mi + 0];
            out[base1 + 2LL * b + 1] = mesh[2 * mi + 1];
        }
        if (out_size >= base1 + 3LL * B) {
            out[base1 + 2LL * B + b] = (float)mi;
        }
    }
}

// ---------------------------------------------------------------------------
// Fallback brute force (only if L exceeds static scratch) — round-1 kernels.
// ---------------------------------------------------------------------------
#define TILE   1024
#define MAXBLK 2048
#define MAXB   512
__device__ float g_pmin[MAXBLK * MAXB];
__device__ int   g_pidx[MAXBLK * MAXB];

__global__ void __launch_bounds__(256)
argmin_partial(const float* __restrict__ mesh, const float* __restrict__ recv,
               float* __restrict__ out, int L, int B)
{
    __shared__ float2 s_pts[TILE];
    const int blk = blockIdx.x, tid = threadIdx.x;
    const int p0 = blk * TILE;
    const int npts = min(TILE, L - p0);
    for (int i = tid; i < npts; i += 256) {
        float2 p = reinterpret_cast<const float2*>(mesh)[p0 + i];
        s_pts[i] = p;
        const int r = p0 + i;
        out[3 * r + 0] = p.x; out[3 * r + 1] = p.y; out[3 * r + 2] = 0.0f;
    }
    __syncthreads();
    float rx = 0.f, ry = 0.f;
    if (tid < B) { rx = recv[3 * tid]; ry = recv[3 * tid + 1]; }
    float vmin = FLT_MAX; int imin = 0;
    #pragma unroll 4
    for (int i = 0; i < npts; i++) {
        const float dx = s_pts[i].x - rx, dy = s_pts[i].y - ry;
        const float v = fmaf(dx, dx, dy * dy);
        if (v < vmin) { vmin = v; imin = p0 + i; }
    }
    if (tid < B) { g_pmin[blk * B + tid] = vmin; g_pidx[blk * B + tid] = imin; }
}

__global__ void __launch_bounds__(256)
argmin_finalize(const float* __restrict__ mesh, float* __restrict__ out,
                int L, int B, int nblk, long long out_size)
{
    const int b = blockIdx.x, tid = threadIdx.x;
    float vmin = FLT_MAX; int imin = 0x7fffffff;
    for (int k = tid; k < nblk; k += 256) {
        const float v = g_pmin[k * B + b]; const int i = g_pidx[k * B + b];
        if (v < vmin || (v == vmin && i < imin)) { vmin = v; imin = i; }
    }
    __shared__ float sv[256]; __shared__ int si[256];
    sv[tid] = vmin; si[tid] = imin; __syncthreads();
    for (int s = 128; s > 0; s >>= 1) {
        if (tid < s) {
            const float v = sv[tid + s]; const int i = si[tid + s];
            if (v < sv[tid] || (v == sv[tid] && i < si[tid])) { sv[tid] = v; si[tid] = i; }
        }
        __syncthreads();
    }
    if (tid == 0) {
        const int mi = si[0];
        const long long base1 = 3LL * L;
        out[3LL * mi + 2] = 1.0f;
        if (b == 0 && B > 1) out[2] = 1.0f;
        if (out_size >= base1 + 2LL * B) {
            out[base1 + 2LL * b + 0] = mesh[2 * mi + 0];
            out[base1 + 2LL * b + 1] = mesh[2 * mi + 1];
        }
        if (out_size >= base1 + 3LL * B)
            out[base1 + 2LL * B + b] = (float)mi;
    }
}

extern "C" void kernel_launch(void* const* d_in, const int* in_sizes, int n_in,
                              void* d_out, int out_size)
{
    const float* mesh = (const float*)d_in[0];
    const float* recv = (const float*)d_in[1];
    float* out = (float*)d_out;

    const int L = in_sizes[0] / 2;
    const int B = in_sizes[1] / 3;

    if (L <= MAXL && B <= 4096) {
        zero_counts<<<(NBINS + 255) / 256, 256>>>();
        bin_count<<<2048, 256>>>(mesh, out, L);
        scan_bins<<<1, 256>>>(L);
        bin_scatter<<<2048, 256>>>(mesh, L);
        nn_search<<<(B + 7) / 8, 256>>>(mesh, recv, out, L, B, (long long)out_size);
    } else {
        int nblk = (L + TILE - 1) / TILE;
        if (nblk > MAXBLK) nblk = MAXBLK;
        argmin_partial<<<nblk, 256>>>(mesh, recv, out, L, B);
        argmin_finalize<<<B, 256>>>(mesh, out, L, B, nblk, (long long)out_size);
    }
}